// round 1
// baseline (speedup 1.0000x reference)
#include <cuda_runtime.h>

// Problem constants
#define BB 2
#define TT 2048
#define CC 1024
#define HH 16
#define DD 64
#define MM (BB*TT)          // 4096

// Scratch (device globals; no allocation allowed)
__device__ float g_q[BB*HH*TT*DD];     // [b,h,t,d]
__device__ float g_k[BB*HH*TT*DD];
__device__ float g_v[BB*HH*TT*DD];
__device__ float g_attn[MM*CC];        // [b,t,c]

// ---------------------------------------------------------------------------
// SGEMM 128x128 tile, Ktile=8, 256 threads, 8x8 per thread (split 4+4).
// MODE 0: QKV projection (blockIdx.z selects W/b), writes to g_q/g_k/g_v in
//         [b,h,t,d] layout.
// MODE 1: output projection, A = g_attn, writes row-major to Cout.
// ---------------------------------------------------------------------------
template<int MODE>
__global__ __launch_bounds__(256)
void sgemm_kernel(const float* __restrict__ A,
                  const float* __restrict__ W0, const float* __restrict__ b0,
                  const float* __restrict__ W1, const float* __restrict__ b1,
                  const float* __restrict__ W2, const float* __restrict__ b2,
                  float* __restrict__ Cout)
{
    __shared__ float As[8*128];
    __shared__ float Bs[8*128];

    const int tid = threadIdx.x;
    const int tx = tid & 15;          // 0..15 (col group)
    const int ty = tid >> 4;          // 0..15 (row group)
    const int bm = blockIdx.y * 128;
    const int bn = blockIdx.x * 128;

    const float* W;
    const float* bias;
    if (MODE == 0) {
        const int z = blockIdx.z;
        W    = (z == 0) ? W0 : (z == 1) ? W1 : W2;
        bias = (z == 0) ? b0 : (z == 1) ? b1 : b2;
    } else {
        W = W0; bias = b0;
    }
    const float* Ap = (MODE == 0) ? A : g_attn;

    // load indices
    const int arow = tid >> 1;             // 0..127
    const int acol = (tid & 1) * 4;        // 0 or 4
    const int brow = tid >> 5;             // 0..7
    const int bcol = (tid & 31) * 4;       // 0..124

    float acc[8][8];
    #pragma unroll
    for (int i = 0; i < 8; i++)
        #pragma unroll
        for (int j = 0; j < 8; j++) acc[i][j] = 0.0f;

    const float* Aptr = Ap + (bm + arow) * 1024 + acol;
    const float* Wptr = W + brow * 1024 + bn + bcol;

    for (int kt = 0; kt < 128; kt++) {
        const float4 av = *(const float4*)(Aptr + kt * 8);
        const float4 bv = *(const float4*)(Wptr + kt * 8192);
        __syncthreads();
        As[(acol + 0) * 128 + arow] = av.x;
        As[(acol + 1) * 128 + arow] = av.y;
        As[(acol + 2) * 128 + arow] = av.z;
        As[(acol + 3) * 128 + arow] = av.w;
        *(float4*)&Bs[brow * 128 + bcol] = bv;
        __syncthreads();

        #pragma unroll
        for (int kk = 0; kk < 8; kk++) {
            const float4 a0 = *(const float4*)&As[kk * 128 + ty * 4];
            const float4 a1 = *(const float4*)&As[kk * 128 + 64 + ty * 4];
            const float4 v0 = *(const float4*)&Bs[kk * 128 + tx * 4];
            const float4 v1 = *(const float4*)&Bs[kk * 128 + 64 + tx * 4];
            const float a_[8] = {a0.x, a0.y, a0.z, a0.w, a1.x, a1.y, a1.z, a1.w};
            const float b_[8] = {v0.x, v0.y, v0.z, v0.w, v1.x, v1.y, v1.z, v1.w};
            #pragma unroll
            for (int i = 0; i < 8; i++)
                #pragma unroll
                for (int j = 0; j < 8; j++)
                    acc[i][j] += a_[i] * b_[j];
        }
    }

    // bias for this thread's 8 columns
    float bb_[8];
    #pragma unroll
    for (int cj = 0; cj < 2; cj++)
        #pragma unroll
        for (int j2 = 0; j2 < 4; j2++)
            bb_[cj * 4 + j2] = bias[bn + cj * 64 + tx * 4 + j2];

    if (MODE == 0) {
        const int z = blockIdx.z;
        float* dst = (z == 0) ? g_q : (z == 1) ? g_k : g_v;
        #pragma unroll
        for (int ri = 0; ri < 2; ri++)
            #pragma unroll
            for (int i2 = 0; i2 < 4; i2++) {
                const int rg = bm + ri * 64 + ty * 4 + i2;
                const int b  = rg >> 11;       // /T
                const int t  = rg & 2047;
                #pragma unroll
                for (int cj = 0; cj < 2; cj++) {
                    const int cg = bn + cj * 64 + tx * 4;
                    const int h  = cg >> 6;
                    const int dd = cg & 63;
                    float4 v;
                    v.x = acc[ri * 4 + i2][cj * 4 + 0] + bb_[cj * 4 + 0];
                    v.y = acc[ri * 4 + i2][cj * 4 + 1] + bb_[cj * 4 + 1];
                    v.z = acc[ri * 4 + i2][cj * 4 + 2] + bb_[cj * 4 + 2];
                    v.w = acc[ri * 4 + i2][cj * 4 + 3] + bb_[cj * 4 + 3];
                    *(float4*)&dst[(((b * HH) + h) * TT + t) * DD + dd] = v;
                }
            }
    } else {
        #pragma unroll
        for (int ri = 0; ri < 2; ri++)
            #pragma unroll
            for (int i2 = 0; i2 < 4; i2++) {
                const int rg = bm + ri * 64 + ty * 4 + i2;
                #pragma unroll
                for (int cj = 0; cj < 2; cj++) {
                    const int cg = bn + cj * 64 + tx * 4;
                    float4 v;
                    v.x = acc[ri * 4 + i2][cj * 4 + 0] + bb_[cj * 4 + 0];
                    v.y = acc[ri * 4 + i2][cj * 4 + 1] + bb_[cj * 4 + 1];
                    v.z = acc[ri * 4 + i2][cj * 4 + 2] + bb_[cj * 4 + 2];
                    v.w = acc[ri * 4 + i2][cj * 4 + 3] + bb_[cj * 4 + 3];
                    *(float4*)&Cout[rg * 1024 + cg] = v;
                }
            }
    }
}

// ---------------------------------------------------------------------------
// fp32 flash-attention, causal. 64x64 tiles, 256 threads (16x16, 4x4/thread).
// Online softmax with exp2f; row reductions via shfl-xor across 16 lanes.
// Smem stride 76 -> conflict-free LDS.128 for the K^T-style access.
// ---------------------------------------------------------------------------
#define SMS 76
#define ATTN_SMEM (3 * 64 * SMS * 4)

__global__ __launch_bounds__(256)
void attn_kernel()
{
    extern __shared__ float sm[];
    float* Qs  = sm;                 // [64][SMS]
    float* KVs = sm + 64 * SMS;      // [64][SMS]
    float* Ps  = sm + 2 * 64 * SMS;  // [64][SMS]

    const int tid = threadIdx.x;
    const int tx = tid & 15;
    const int ty = tid >> 4;
    const int qb = blockIdx.x;       // query tile 0..31
    const int bh = blockIdx.y;       // 0..31

    const float* Qg = g_q + bh * TT * DD;
    const float* Kg = g_k + bh * TT * DD;
    const float* Vg = g_v + bh * TT * DD;

    // load Q tile
    #pragma unroll
    for (int it = 0; it < 4; it++) {
        const int slot = tid + it * 256;
        const int r  = slot >> 4;
        const int c4 = (slot & 15) * 4;
        *(float4*)&Qs[r * SMS + c4] = *(const float4*)&Qg[(qb * 64 + r) * 64 + c4];
    }

    float o[4][4];
    float mI[4], lI[4];
    #pragma unroll
    for (int i = 0; i < 4; i++) {
        mI[i] = -1e30f; lI[i] = 0.0f;
        #pragma unroll
        for (int j = 0; j < 4; j++) o[i][j] = 0.0f;
    }
    const float SC = 0.125f * 1.44269504088896340736f;  // (1/sqrt(64)) * log2(e)

    for (int kt = 0; kt <= qb; kt++) {
        __syncthreads();
        // K tile
        #pragma unroll
        for (int it = 0; it < 4; it++) {
            const int slot = tid + it * 256;
            const int r  = slot >> 4;
            const int c4 = (slot & 15) * 4;
            *(float4*)&KVs[r * SMS + c4] = *(const float4*)&Kg[(kt * 64 + r) * 64 + c4];
        }
        __syncthreads();

        float s[4][4];
        #pragma unroll
        for (int i = 0; i < 4; i++)
            #pragma unroll
            for (int j = 0; j < 4; j++) s[i][j] = 0.0f;

        #pragma unroll 4
        for (int k4 = 0; k4 < 64; k4 += 4) {
            float4 qv[4], kv[4];
            #pragma unroll
            for (int i = 0; i < 4; i++) qv[i] = *(const float4*)&Qs[(ty * 4 + i) * SMS + k4];
            #pragma unroll
            for (int j = 0; j < 4; j++) kv[j] = *(const float4*)&KVs[(tx * 4 + j) * SMS + k4];
            #pragma unroll
            for (int i = 0; i < 4; i++)
                #pragma unroll
                for (int j = 0; j < 4; j++)
                    s[i][j] += qv[i].x * kv[j].x + qv[i].y * kv[j].y
                             + qv[i].z * kv[j].z + qv[i].w * kv[j].w;
        }

        const bool diag = (kt == qb);
        #pragma unroll
        for (int i = 0; i < 4; i++) {
            const int rg = qb * 64 + ty * 4 + i;
            float z[4];
            #pragma unroll
            for (int j = 0; j < 4; j++) {
                const int cg = kt * 64 + tx * 4 + j;
                z[j] = (diag && (cg > rg)) ? -1e30f : s[i][j] * SC;
            }
            float mx = fmaxf(fmaxf(z[0], z[1]), fmaxf(z[2], z[3]));
            #pragma unroll
            for (int off = 8; off >= 1; off >>= 1)
                mx = fmaxf(mx, __shfl_xor_sync(0xffffffffu, mx, off));
            const float mN = fmaxf(mI[i], mx);
            const float corr = exp2f(mI[i] - mN);
            mI[i] = mN;
            float4 p;
            p.x = exp2f(z[0] - mN);
            p.y = exp2f(z[1] - mN);
            p.z = exp2f(z[2] - mN);
            p.w = exp2f(z[3] - mN);
            float rs = p.x + p.y + p.z + p.w;
            #pragma unroll
            for (int off = 8; off >= 1; off >>= 1)
                rs += __shfl_xor_sync(0xffffffffu, rs, off);
            lI[i] = lI[i] * corr + rs;
            #pragma unroll
            for (int j = 0; j < 4; j++) o[i][j] *= corr;
            *(float4*)&Ps[(ty * 4 + i) * SMS + tx * 4] = p;
        }

        __syncthreads();
        // V tile (reuse KVs)
        #pragma unroll
        for (int it = 0; it < 4; it++) {
            const int slot = tid + it * 256;
            const int r  = slot >> 4;
            const int c4 = (slot & 15) * 4;
            *(float4*)&KVs[r * SMS + c4] = *(const float4*)&Vg[(kt * 64 + r) * 64 + c4];
        }
        __syncthreads();

        #pragma unroll 4
        for (int k4 = 0; k4 < 64; k4 += 4) {
            const float4 vr0 = *(const float4*)&KVs[(k4 + 0) * SMS + tx * 4];
            const float4 vr1 = *(const float4*)&KVs[(k4 + 1) * SMS + tx * 4];
            const float4 vr2 = *(const float4*)&KVs[(k4 + 2) * SMS + tx * 4];
            const float4 vr3 = *(const float4*)&KVs[(k4 + 3) * SMS + tx * 4];
            #pragma unroll
            for (int i = 0; i < 4; i++) {
                const float4 pp = *(const float4*)&Ps[(ty * 4 + i) * SMS + k4];
                o[i][0] += pp.x * vr0.x + pp.y * vr1.x + pp.z * vr2.x + pp.w * vr3.x;
                o[i][1] += pp.x * vr0.y + pp.y * vr1.y + pp.z * vr2.y + pp.w * vr3.y;
                o[i][2] += pp.x * vr0.z + pp.y * vr1.z + pp.z * vr2.z + pp.w * vr3.z;
                o[i][3] += pp.x * vr0.w + pp.y * vr1.w + pp.z * vr2.w + pp.w * vr3.w;
            }
        }
    }

    // write to g_attn in [b,t,c] layout
    const int b = bh >> 4;
    const int h = bh & 15;
    #pragma unroll
    for (int i = 0; i < 4; i++) {
        const float inv = 1.0f / lI[i];
        const int t = qb * 64 + ty * 4 + i;
        float4 v;
        v.x = o[i][0] * inv;
        v.y = o[i][1] * inv;
        v.z = o[i][2] * inv;
        v.w = o[i][3] * inv;
        *(float4*)&g_attn[(b * TT + t) * CC + h * 64 + tx * 4] = v;
    }
}

// ---------------------------------------------------------------------------
extern "C" void kernel_launch(void* const* d_in, const int* in_sizes, int n_in,
                              void* d_out, int out_size)
{
    const float* x  = (const float*)d_in[0];
    const float* Wq = (const float*)d_in[1];
    const float* bq = (const float*)d_in[2];
    const float* Wk = (const float*)d_in[3];
    const float* bk = (const float*)d_in[4];
    const float* Wv = (const float*)d_in[5];
    const float* bv = (const float*)d_in[6];
    const float* Wo = (const float*)d_in[7];
    const float* bo = (const float*)d_in[8];
    float* out = (float*)d_out;

    // QKV projections
    sgemm_kernel<0><<<dim3(8, 32, 3), 256>>>(x, Wq, bq, Wk, bk, Wv, bv, nullptr);

    // attention
    cudaFuncSetAttribute(attn_kernel, cudaFuncAttributeMaxDynamicSharedMemorySize, ATTN_SMEM);
    attn_kernel<<<dim3(32, 32), 256, ATTN_SMEM>>>();

    // output projection
    sgemm_kernel<1><<<dim3(8, 32), 256>>>(x, Wo, bo, nullptr, nullptr, nullptr, nullptr, out);
}

// round 3
// speedup vs baseline: 1.1566x; 1.1566x over previous
#include <cuda_runtime.h>
#include <cuda_bf16.h>
#include <cstdint>

// Problem constants
#define BB 2
#define TT 2048
#define CC 1024
#define HH 16
#define DD 64
#define MMr (BB*TT)          // 4096

// ---------------- scratch (device globals; no allocation allowed) ----------
__device__ float g_q[BB*HH*TT*DD];     // [b,h,t,d]
__device__ float g_k[BB*HH*TT*DD];
__device__ float g_v[BB*HH*TT*DD];
__device__ float g_attn[MMr*CC];       // [b,t,c]

__device__ __nv_bfloat16 g_xh[MMr*CC];
__device__ __nv_bfloat16 g_xl[MMr*CC];
__device__ __nv_bfloat16 g_ah[MMr*CC];
__device__ __nv_bfloat16 g_al[MMr*CC];
__device__ __nv_bfloat16 g_wth[4*CC*CC];   // W^T hi, [n][k], 4 matrices
__device__ __nv_bfloat16 g_wtl[4*CC*CC];   // W^T lo

// ---------------- helpers ---------------------------------------------------
__device__ __forceinline__ uint32_t smem_u32(const void* p) {
    uint32_t a;
    asm("{ .reg .u64 t; cvta.to.shared.u64 t, %1; cvt.u32.u64 %0, t; }"
        : "=r"(a) : "l"(p));
    return a;
}

#define CP_ASYNC16(s, g) \
    asm volatile("cp.async.cg.shared.global [%0], [%1], 16;" :: "r"(s), "l"(g) : "memory")
#define CP_COMMIT()  asm volatile("cp.async.commit_group;" ::: "memory")
#define CP_WAIT(n)   asm volatile("cp.async.wait_group %0;" :: "n"(n) : "memory")

__device__ __forceinline__ void ldmx4(uint32_t* r, uint32_t addr) {
    asm volatile("ldmatrix.sync.aligned.m8n8.x4.shared.b16 {%0,%1,%2,%3}, [%4];"
        : "=r"(r[0]), "=r"(r[1]), "=r"(r[2]), "=r"(r[3]) : "r"(addr));
}
__device__ __forceinline__ void mma16816(float* c, const uint32_t* a, const uint32_t* b) {
    asm volatile(
        "mma.sync.aligned.m16n8k16.row.col.f32.bf16.bf16.f32 "
        "{%0,%1,%2,%3}, {%4,%5,%6,%7}, {%8,%9}, {%0,%1,%2,%3};"
        : "+f"(c[0]), "+f"(c[1]), "+f"(c[2]), "+f"(c[3])
        : "r"(a[0]), "r"(a[1]), "r"(a[2]), "r"(a[3]), "r"(b[0]), "r"(b[1]));
}

// ---------------------------------------------------------------------------
// bf16 HMMA split GEMM.  C[M=4096, N=1024] = A * W + bias.
// A = Ah + Al (bf16 split of fp32).  B = W^T rows [n][k] bf16 hi/lo.
// 3 accumulation passes: Ah*Bh, Ah*Bl, Al*Bh -> fp32 accumulators.
// Tile 128x128, BK=32, cp.async 3-stage ring, 8 warps (4m x 2n), warp 32x64.
// MODE 0: z=blockIdx.z picks {Wq,Wk,Wv}; scatter to g_q/g_k/g_v [b,h,t,d].
// MODE 1: Wo; write row-major to outp.
// ---------------------------------------------------------------------------
#define SAB 80                       // smem row stride, bytes (40 halves)
#define A_BYTES (128*SAB)            // 10240
#define STAGE_BYTES (2*A_BYTES)      // 20480
#define NS 3
#define GEMM_SMEM (NS*STAGE_BYTES)   // 61440
#define NITER 96                     // 3 passes * (1024/32)

template<int MODE>
__global__ __launch_bounds__(256, 1)
void gemm_tc(const __nv_bfloat16* __restrict__ Ah,
             const __nv_bfloat16* __restrict__ Al,
             float* __restrict__ outp,
             const float* __restrict__ bias0,
             const float* __restrict__ bias1,
             const float* __restrict__ bias2)
{
    extern __shared__ __align__(128) char dsm[];

    const int tid    = threadIdx.x;
    const int wid    = tid >> 5;
    const int lane   = tid & 31;
    const int warp_m = wid & 3;          // 4 -> 32 rows each
    const int warp_n = wid >> 2;         // 2 -> 64 cols each
    const int bn     = blockIdx.x * 128;
    const int bm     = blockIdx.y * 128;
    const int z      = (MODE == 0) ? blockIdx.z : 3;

    const __nv_bfloat16* Bh = g_wth + (size_t)z * (CC * CC);
    const __nv_bfloat16* Bl = g_wtl + (size_t)z * (CC * CC);
    const float* bias = (MODE == 0) ? ((z == 0) ? bias0 : (z == 1) ? bias1 : bias2) : bias0;

    const uint32_t smem_base = smem_u32(dsm);

    float acc[2][8][4];
    #pragma unroll
    for (int mt = 0; mt < 2; mt++)
        #pragma unroll
        for (int nt = 0; nt < 8; nt++)
            #pragma unroll
            for (int e = 0; e < 4; e++) acc[mt][nt][e] = 0.0f;

    // stage loader: A[128 x 32] + B[128 x 32] bf16, 16B chunks via cp.async
    auto load_stage = [&](int L) {
        const int slot = L % NS;
        const int pass = L >> 5;              // 0,1,2
        const int kt   = (L & 31) * 32;
        const __nv_bfloat16* As = (pass < 2) ? Ah : Al;
        const __nv_bfloat16* Bs = (pass == 1) ? Bl : Bh;
        const uint32_t sA = smem_base + slot * STAGE_BYTES;
        const uint32_t sB = sA + A_BYTES;
        #pragma unroll
        for (int i = 0; i < 2; i++) {
            const int idx = i * 256 + tid;
            const int r = idx >> 2, c = idx & 3;     // row, 16B chunk
            CP_ASYNC16(sA + r * SAB + c * 16,
                       As + (size_t)(bm + r) * CC + kt + c * 8);
        }
        #pragma unroll
        for (int i = 0; i < 2; i++) {
            const int idx = i * 256 + tid;
            const int r = idx >> 2, c = idx & 3;
            CP_ASYNC16(sB + r * SAB + c * 16,
                       Bs + (size_t)(bn + r) * CC + kt + c * 8);
        }
    };

    // prologue
    #pragma unroll
    for (int L = 0; L < NS - 1; L++) { load_stage(L); CP_COMMIT(); }

    for (int it = 0; it < NITER; it++) {
        const int L = it + NS - 1;
        if (L < NITER) load_stage(L);
        CP_COMMIT();
        CP_WAIT(NS - 1);
        __syncthreads();

        const uint32_t sA = smem_base + (it % NS) * STAGE_BYTES;
        const uint32_t sB = sA + A_BYTES;
        const uint32_t aBase = sA + (warp_m * 32 + (lane & 15)) * SAB + (lane >> 4) * 16;
        const uint32_t bBase = sB + (warp_n * 64 + (lane & 7) + ((lane >> 4) << 3)) * SAB
                                  + ((lane >> 3) & 1) * 16;
        #pragma unroll
        for (int kk = 0; kk < 2; kk++) {       // k = 0, 16
            uint32_t a[2][4], b[4][4];
            ldmx4(a[0], aBase + kk * 32);
            ldmx4(a[1], aBase + 16 * SAB + kk * 32);
            #pragma unroll
            for (int np = 0; np < 4; np++)
                ldmx4(b[np], bBase + np * 16 * SAB + kk * 32);
            #pragma unroll
            for (int mt = 0; mt < 2; mt++)
                #pragma unroll
                for (int np = 0; np < 4; np++) {
                    mma16816(acc[mt][np * 2 + 0], a[mt], &b[np][0]);
                    mma16816(acc[mt][np * 2 + 1], a[mt], &b[np][2]);
                }
        }
        __syncthreads();   // protect slot reuse by next iteration's loads
    }

    // epilogue: write accumulators (+bias)
    const int groupID = lane >> 2;
    const int tig     = lane & 3;
    float* dst0 = (MODE == 0) ? ((z == 0) ? g_q : (z == 1) ? g_k : g_v) : outp;

    #pragma unroll
    for (int mt = 0; mt < 2; mt++) {
        #pragma unroll
        for (int nt = 0; nt < 8; nt++) {
            const int col = bn + warp_n * 64 + nt * 8 + tig * 2;
            const float b0 = bias[col], b1 = bias[col + 1];
            #pragma unroll
            for (int half = 0; half < 2; half++) {
                const int rg = bm + warp_m * 32 + mt * 16 + groupID + half * 8;
                float2 v;
                v.x = acc[mt][nt][half * 2 + 0] + b0;
                v.y = acc[mt][nt][half * 2 + 1] + b1;
                if (MODE == 0) {
                    const int b = rg >> 11, t = rg & 2047;
                    const int h = col >> 6, d = col & 63;
                    *(float2*)&dst0[(((size_t)(b * HH + h) * TT + t) * DD) + d] = v;
                } else {
                    *(float2*)&dst0[(size_t)rg * CC + col] = v;
                }
            }
        }
    }
}

// ---------------------------------------------------------------------------
// fp32 -> (hi, lo) bf16 split, vectorized by float4
// ---------------------------------------------------------------------------
__global__ __launch_bounds__(256)
void split_f32(const float4* __restrict__ in, __nv_bfloat16* __restrict__ hi,
               __nv_bfloat16* __restrict__ lo)
{
    const int i = blockIdx.x * 256 + threadIdx.x;
    const float4 v = in[i];
    __nv_bfloat16 h0 = __float2bfloat16(v.x);
    __nv_bfloat16 h1 = __float2bfloat16(v.y);
    __nv_bfloat16 h2 = __float2bfloat16(v.z);
    __nv_bfloat16 h3 = __float2bfloat16(v.w);
    ushort4 H, L;
    H.x = __bfloat16_as_ushort(h0); H.y = __bfloat16_as_ushort(h1);
    H.z = __bfloat16_as_ushort(h2); H.w = __bfloat16_as_ushort(h3);
    L.x = __bfloat16_as_ushort(__float2bfloat16(v.x - __bfloat162float(h0)));
    L.y = __bfloat16_as_ushort(__float2bfloat16(v.y - __bfloat162float(h1)));
    L.z = __bfloat16_as_ushort(__float2bfloat16(v.z - __bfloat162float(h2)));
    L.w = __bfloat16_as_ushort(__float2bfloat16(v.w - __bfloat162float(h3)));
    *(ushort4*)(hi + (size_t)i * 4) = H;
    *(ushort4*)(lo + (size_t)i * 4) = L;
}

// ---------------------------------------------------------------------------
// Transpose + split all 4 weight matrices: W[k][n] fp32 -> Wt hi/lo [n][k] bf16
// ---------------------------------------------------------------------------
__global__ __launch_bounds__(256)
void transpose_split_w(const float* __restrict__ Wq, const float* __restrict__ Wk,
                       const float* __restrict__ Wv, const float* __restrict__ Wo)
{
    __shared__ float tile[32][33];
    const int zz = blockIdx.z;
    const float* W = (zz == 0) ? Wq : (zz == 1) ? Wk : (zz == 2) ? Wv : Wo;
    const int tx = threadIdx.x, ty = threadIdx.y;
    const int n0 = blockIdx.x * 32;   // n block
    const int k0 = blockIdx.y * 32;   // k block
    #pragma unroll
    for (int i = ty; i < 32; i += 8)
        tile[i][tx] = W[(size_t)(k0 + i) * CC + n0 + tx];
    __syncthreads();
    __nv_bfloat16* oh = g_wth + (size_t)zz * (CC * CC);
    __nv_bfloat16* ol = g_wtl + (size_t)zz * (CC * CC);
    #pragma unroll
    for (int i = ty; i < 32; i += 8) {
        const float v = tile[tx][i];                 // = W[k0+tx][n0+i]
        const __nv_bfloat16 h = __float2bfloat16(v);
        oh[(size_t)(n0 + i) * CC + k0 + tx] = h;
        ol[(size_t)(n0 + i) * CC + k0 + tx] = __float2bfloat16(v - __bfloat162float(h));
    }
}

// ---------------------------------------------------------------------------
// fp32 flash-attention, causal (unchanged, known-good)
// ---------------------------------------------------------------------------
#define SMS 76
#define ATTN_SMEM (3 * 64 * SMS * 4)

__global__ __launch_bounds__(256)
void attn_kernel()
{
    extern __shared__ float sm[];
    float* Qs  = sm;
    float* KVs = sm + 64 * SMS;
    float* Ps  = sm + 2 * 64 * SMS;

    const int tid = threadIdx.x;
    const int tx = tid & 15;
    const int ty = tid >> 4;
    const int qb = blockIdx.x;
    const int bh = blockIdx.y;

    const float* Qg = g_q + (size_t)bh * TT * DD;
    const float* Kg = g_k + (size_t)bh * TT * DD;
    const float* Vg = g_v + (size_t)bh * TT * DD;

    #pragma unroll
    for (int it = 0; it < 4; it++) {
        const int slot = tid + it * 256;
        const int r  = slot >> 4;
        const int c4 = (slot & 15) * 4;
        *(float4*)&Qs[r * SMS + c4] = *(const float4*)&Qg[(qb * 64 + r) * 64 + c4];
    }

    float o[4][4];
    float mI[4], lI[4];
    #pragma unroll
    for (int i = 0; i < 4; i++) {
        mI[i] = -1e30f; lI[i] = 0.0f;
        #pragma unroll
        for (int j = 0; j < 4; j++) o[i][j] = 0.0f;
    }
    const float SC = 0.125f * 1.44269504088896340736f;

    for (int kt = 0; kt <= qb; kt++) {
        __syncthreads();
        #pragma unroll
        for (int it = 0; it < 4; it++) {
            const int slot = tid + it * 256;
            const int r  = slot >> 4;
            const int c4 = (slot & 15) * 4;
            *(float4*)&KVs[r * SMS + c4] = *(const float4*)&Kg[(kt * 64 + r) * 64 + c4];
        }
        __syncthreads();

        float s[4][4];
        #pragma unroll
        for (int i = 0; i < 4; i++)
            #pragma unroll
            for (int j = 0; j < 4; j++) s[i][j] = 0.0f;

        #pragma unroll 4
        for (int k4 = 0; k4 < 64; k4 += 4) {
            float4 qv[4], kv[4];
            #pragma unroll
            for (int i = 0; i < 4; i++) qv[i] = *(const float4*)&Qs[(ty * 4 + i) * SMS + k4];
            #pragma unroll
            for (int j = 0; j < 4; j++) kv[j] = *(const float4*)&KVs[(tx * 4 + j) * SMS + k4];
            #pragma unroll
            for (int i = 0; i < 4; i++)
                #pragma unroll
                for (int j = 0; j < 4; j++)
                    s[i][j] += qv[i].x * kv[j].x + qv[i].y * kv[j].y
                             + qv[i].z * kv[j].z + qv[i].w * kv[j].w;
        }

        const bool diag = (kt == qb);
        #pragma unroll
        for (int i = 0; i < 4; i++) {
            const int rg = qb * 64 + ty * 4 + i;
            float zv[4];
            #pragma unroll
            for (int j = 0; j < 4; j++) {
                const int cg = kt * 64 + tx * 4 + j;
                zv[j] = (diag && (cg > rg)) ? -1e30f : s[i][j] * SC;
            }
            float mx = fmaxf(fmaxf(zv[0], zv[1]), fmaxf(zv[2], zv[3]));
            #pragma unroll
            for (int off = 8; off >= 1; off >>= 1)
                mx = fmaxf(mx, __shfl_xor_sync(0xffffffffu, mx, off));
            const float mN = fmaxf(mI[i], mx);
            const float corr = exp2f(mI[i] - mN);
            mI[i] = mN;
            float4 p;
            p.x = exp2f(zv[0] - mN);
            p.y = exp2f(zv[1] - mN);
            p.z = exp2f(zv[2] - mN);
            p.w = exp2f(zv[3] - mN);
            float rs = p.x + p.y + p.z + p.w;
            #pragma unroll
            for (int off = 8; off >= 1; off >>= 1)
                rs += __shfl_xor_sync(0xffffffffu, rs, off);
            lI[i] = lI[i] * corr + rs;
            #pragma unroll
            for (int j = 0; j < 4; j++) o[i][j] *= corr;
            *(float4*)&Ps[(ty * 4 + i) * SMS + tx * 4] = p;
        }

        __syncthreads();
        #pragma unroll
        for (int it = 0; it < 4; it++) {
            const int slot = tid + it * 256;
            const int r  = slot >> 4;
            const int c4 = (slot & 15) * 4;
            *(float4*)&KVs[r * SMS + c4] = *(const float4*)&Vg[(kt * 64 + r) * 64 + c4];
        }
        __syncthreads();

        #pragma unroll 4
        for (int k4 = 0; k4 < 64; k4 += 4) {
            const float4 vr0 = *(const float4*)&KVs[(k4 + 0) * SMS + tx * 4];
            const float4 vr1 = *(const float4*)&KVs[(k4 + 1) * SMS + tx * 4];
            const float4 vr2 = *(const float4*)&KVs[(k4 + 2) * SMS + tx * 4];
            const float4 vr3 = *(const float4*)&KVs[(k4 + 3) * SMS + tx * 4];
            #pragma unroll
            for (int i = 0; i < 4; i++) {
                const float4 pp = *(const float4*)&Ps[(ty * 4 + i) * SMS + k4];
                o[i][0] += pp.x * vr0.x + pp.y * vr1.x + pp.z * vr2.x + pp.w * vr3.x;
                o[i][1] += pp.x * vr0.y + pp.y * vr1.y + pp.z * vr2.y + pp.w * vr3.y;
                o[i][2] += pp.x * vr0.z + pp.y * vr1.z + pp.z * vr2.z + pp.w * vr3.z;
                o[i][3] += pp.x * vr0.w + pp.y * vr1.w + pp.z * vr2.w + pp.w * vr3.w;
            }
        }
    }

    const int b = bh >> 4;
    const int h = bh & 15;
    #pragma unroll
    for (int i = 0; i < 4; i++) {
        const float inv = 1.0f / lI[i];
        const int t = qb * 64 + ty * 4 + i;
        float4 v;
        v.x = o[i][0] * inv;
        v.y = o[i][1] * inv;
        v.z = o[i][2] * inv;
        v.w = o[i][3] * inv;
        *(float4*)&g_attn[((size_t)(b * TT) + t) * CC + h * 64 + tx * 4] = v;
    }
}

// ---------------------------------------------------------------------------
extern "C" void kernel_launch(void* const* d_in, const int* in_sizes, int n_in,
                              void* d_out, int out_size)
{
    const float* x  = (const float*)d_in[0];
    const float* Wq = (const float*)d_in[1];
    const float* bq = (const float*)d_in[2];
    const float* Wk = (const float*)d_in[3];
    const float* bk = (const float*)d_in[4];
    const float* Wv = (const float*)d_in[5];
    const float* bv = (const float*)d_in[6];
    const float* Wo = (const float*)d_in[7];
    const float* bo = (const float*)d_in[8];
    float* out = (float*)d_out;

    cudaFuncSetAttribute(gemm_tc<0>, cudaFuncAttributeMaxDynamicSharedMemorySize, GEMM_SMEM);
    cudaFuncSetAttribute(gemm_tc<1>, cudaFuncAttributeMaxDynamicSharedMemorySize, GEMM_SMEM);
    cudaFuncSetAttribute(attn_kernel, cudaFuncAttributeMaxDynamicSharedMemorySize, ATTN_SMEM);

    __nv_bfloat16 *xh, *xl, *ah, *al;
    cudaGetSymbolAddress((void**)&xh, g_xh);
    cudaGetSymbolAddress((void**)&xl, g_xl);
    cudaGetSymbolAddress((void**)&ah, g_ah);
    cudaGetSymbolAddress((void**)&al, g_al);

    // split x into bf16 hi/lo, transpose+split all weights
    split_f32<<<MMr * CC / 1024, 256>>>((const float4*)x, xh, xl);
    transpose_split_w<<<dim3(32, 32, 4), dim3(32, 8)>>>(Wq, Wk, Wv, Wo);

    // QKV projections (HMMA)
    gemm_tc<0><<<dim3(8, 32, 3), 256, GEMM_SMEM>>>(xh, xl, nullptr, bq, bk, bv);

    // attention (fp32)
    attn_kernel<<<dim3(32, 32), 256, ATTN_SMEM>>>();

    // split attention output, then output projection (HMMA)
    float* attn_ptr;
    cudaGetSymbolAddress((void**)&attn_ptr, g_attn);
    split_f32<<<MMr * CC / 1024, 256>>>((const float4*)attn_ptr, ah, al);
    gemm_tc<1><<<dim3(8, 32, 1), 256, GEMM_SMEM>>>(ah, al, out, bo, bo, bo);
}

// round 4
// speedup vs baseline: 2.2737x; 1.9659x over previous
#include <cuda_runtime.h>
#include <cuda_bf16.h>
#include <cstdint>

// Problem constants
#define BB 2
#define TT 2048
#define CC 1024
#define HH 16
#define DD 64
#define MMr (BB*TT)          // 4096

// ---------------- scratch (device globals; no allocation allowed) ----------
__device__ __nv_bfloat16 g_xh[MMr*CC];
__device__ __nv_bfloat16 g_xl[MMr*CC];
__device__ __nv_bfloat16 g_ah[MMr*CC];      // attn output hi [b,t,c]
__device__ __nv_bfloat16 g_al[MMr*CC];      // attn output lo
__device__ __nv_bfloat16 g_wth[4*CC*CC];    // W^T hi, [n][k], 4 matrices
__device__ __nv_bfloat16 g_wtl[4*CC*CC];    // W^T lo
__device__ __nv_bfloat16 g_qh[BB*HH*TT*DD]; // [b,h,t,d]
__device__ __nv_bfloat16 g_ql[BB*HH*TT*DD];
__device__ __nv_bfloat16 g_kh[BB*HH*TT*DD]; // [b,h,t,d]
__device__ __nv_bfloat16 g_kl[BB*HH*TT*DD];
__device__ __nv_bfloat16 g_vth[BB*HH*DD*TT]; // V^T [b,h,d,t]
__device__ __nv_bfloat16 g_vtl[BB*HH*DD*TT];

// ---------------- helpers ---------------------------------------------------
__device__ __forceinline__ uint32_t smem_u32(const void* p) {
    uint32_t a;
    asm("{ .reg .u64 t; cvta.to.shared.u64 t, %1; cvt.u32.u64 %0, t; }"
        : "=r"(a) : "l"(p));
    return a;
}

#define CP_ASYNC16(s, g) \
    asm volatile("cp.async.cg.shared.global [%0], [%1], 16;" :: "r"(s), "l"(g) : "memory")
#define CP_COMMIT()  asm volatile("cp.async.commit_group;" ::: "memory")
#define CP_WAIT(n)   asm volatile("cp.async.wait_group %0;" :: "n"(n) : "memory")

__device__ __forceinline__ void ldmx4(uint32_t* r, uint32_t addr) {
    asm volatile("ldmatrix.sync.aligned.m8n8.x4.shared.b16 {%0,%1,%2,%3}, [%4];"
        : "=r"(r[0]), "=r"(r[1]), "=r"(r[2]), "=r"(r[3]) : "r"(addr));
}
__device__ __forceinline__ void mma16816(float* c, const uint32_t* a, const uint32_t* b) {
    asm volatile(
        "mma.sync.aligned.m16n8k16.row.col.f32.bf16.bf16.f32 "
        "{%0,%1,%2,%3}, {%4,%5,%6,%7}, {%8,%9}, {%0,%1,%2,%3};"
        : "+f"(c[0]), "+f"(c[1]), "+f"(c[2]), "+f"(c[3])
        : "r"(a[0]), "r"(a[1]), "r"(a[2]), "r"(a[3]), "r"(b[0]), "r"(b[1]));
}
// pack (c0 -> low, c1 -> high) as bf16x2 (hi) plus residual pair (lo)
__device__ __forceinline__ void split2(float c0, float c1, uint32_t& h, uint32_t& l) {
    const __nv_bfloat16 b0 = __float2bfloat16(c0);
    const __nv_bfloat16 b1 = __float2bfloat16(c1);
    asm("cvt.rn.bf16x2.f32 %0, %1, %2;" : "=r"(h) : "f"(c1), "f"(c0));
    const float r0 = c0 - __bfloat162float(b0);
    const float r1 = c1 - __bfloat162float(b1);
    asm("cvt.rn.bf16x2.f32 %0, %1, %2;" : "=r"(l) : "f"(r1), "f"(r0));
}

// ---------------------------------------------------------------------------
// bf16 HMMA split GEMM.  C[M=4096, N=1024] = A * W + bias.
// 3 accumulation passes: Ah*Bh, Ah*Bl, Al*Bh -> fp32 accumulators.
// Tile 128x128, BK=32, cp.async 3-stage ring, 8 warps (4m x 2n), warp 32x64.
// MODE 0: z selects {Wq,Wk,Wv}; writes bf16 hi/lo Q/K [b,h,t,d], V^T [b,h,d,t].
// MODE 1: Wo; write fp32 row-major to outp.
// ---------------------------------------------------------------------------
#define SAB 80                       // smem row stride, bytes (40 halves)
#define A_BYTES (128*SAB)            // 10240
#define STAGE_BYTES (2*A_BYTES)      // 20480
#define NS 3
#define GEMM_SMEM (NS*STAGE_BYTES)   // 61440
#define NITER 96                     // 3 passes * (1024/32)

template<int MODE>
__global__ __launch_bounds__(256, 1)
void gemm_tc(const __nv_bfloat16* __restrict__ Ah,
             const __nv_bfloat16* __restrict__ Al,
             float* __restrict__ outp,
             const float* __restrict__ bias0,
             const float* __restrict__ bias1,
             const float* __restrict__ bias2)
{
    extern __shared__ __align__(128) char dsm[];

    const int tid    = threadIdx.x;
    const int wid    = tid >> 5;
    const int lane   = tid & 31;
    const int warp_m = wid & 3;
    const int warp_n = wid >> 2;
    const int bn     = blockIdx.x * 128;
    const int bm     = blockIdx.y * 128;
    const int z      = (MODE == 0) ? blockIdx.z : 3;

    const __nv_bfloat16* Bh = g_wth + (size_t)z * (CC * CC);
    const __nv_bfloat16* Bl = g_wtl + (size_t)z * (CC * CC);
    const float* bias = (MODE == 0) ? ((z == 0) ? bias0 : (z == 1) ? bias1 : bias2) : bias0;

    const uint32_t smem_base = smem_u32(dsm);

    float acc[2][8][4];
    #pragma unroll
    for (int mt = 0; mt < 2; mt++)
        #pragma unroll
        for (int nt = 0; nt < 8; nt++)
            #pragma unroll
            for (int e = 0; e < 4; e++) acc[mt][nt][e] = 0.0f;

    auto load_stage = [&](int L) {
        const int slot = L % NS;
        const int pass = L >> 5;
        const int kt   = (L & 31) * 32;
        const __nv_bfloat16* As = (pass < 2) ? Ah : Al;
        const __nv_bfloat16* Bs = (pass == 1) ? Bl : Bh;
        const uint32_t sA = smem_base + slot * STAGE_BYTES;
        const uint32_t sB = sA + A_BYTES;
        #pragma unroll
        for (int i = 0; i < 2; i++) {
            const int idx = i * 256 + tid;
            const int r = idx >> 2, c = idx & 3;
            CP_ASYNC16(sA + r * SAB + c * 16,
                       As + (size_t)(bm + r) * CC + kt + c * 8);
        }
        #pragma unroll
        for (int i = 0; i < 2; i++) {
            const int idx = i * 256 + tid;
            const int r = idx >> 2, c = idx & 3;
            CP_ASYNC16(sB + r * SAB + c * 16,
                       Bs + (size_t)(bn + r) * CC + kt + c * 8);
        }
    };

    #pragma unroll
    for (int L = 0; L < NS - 1; L++) { load_stage(L); CP_COMMIT(); }

    for (int it = 0; it < NITER; it++) {
        const int L = it + NS - 1;
        if (L < NITER) load_stage(L);
        CP_COMMIT();
        CP_WAIT(NS - 1);
        __syncthreads();

        const uint32_t sA = smem_base + (it % NS) * STAGE_BYTES;
        const uint32_t sB = sA + A_BYTES;
        const uint32_t aBase = sA + (warp_m * 32 + (lane & 15)) * SAB + (lane >> 4) * 16;
        const uint32_t bBase = sB + (warp_n * 64 + (lane & 7) + ((lane >> 4) << 3)) * SAB
                                  + ((lane >> 3) & 1) * 16;
        #pragma unroll
        for (int kk = 0; kk < 2; kk++) {
            uint32_t a[2][4], b[4][4];
            ldmx4(a[0], aBase + kk * 32);
            ldmx4(a[1], aBase + 16 * SAB + kk * 32);
            #pragma unroll
            for (int np = 0; np < 4; np++)
                ldmx4(b[np], bBase + np * 16 * SAB + kk * 32);
            #pragma unroll
            for (int mt = 0; mt < 2; mt++)
                #pragma unroll
                for (int np = 0; np < 4; np++) {
                    mma16816(acc[mt][np * 2 + 0], a[mt], &b[np][0]);
                    mma16816(acc[mt][np * 2 + 1], a[mt], &b[np][2]);
                }
        }
        __syncthreads();
    }

    // epilogue
    const int groupID = lane >> 2;
    const int tig     = lane & 3;

    #pragma unroll
    for (int mt = 0; mt < 2; mt++) {
        #pragma unroll
        for (int nt = 0; nt < 8; nt++) {
            const int col = bn + warp_n * 64 + nt * 8 + tig * 2;
            const float b0 = bias[col], b1 = bias[col + 1];
            #pragma unroll
            for (int half = 0; half < 2; half++) {
                const int rg = bm + warp_m * 32 + mt * 16 + groupID + half * 8;
                const float vx = acc[mt][nt][half * 2 + 0] + b0;
                const float vy = acc[mt][nt][half * 2 + 1] + b1;
                if (MODE == 1) {
                    float2 v; v.x = vx; v.y = vy;
                    *(float2*)&outp[(size_t)rg * CC + col] = v;
                } else {
                    const int b = rg >> 11, t = rg & 2047;
                    const int h = col >> 6, d = col & 63;
                    const __nv_bfloat16 hx = __float2bfloat16(vx);
                    const __nv_bfloat16 hy = __float2bfloat16(vy);
                    const __nv_bfloat16 lx = __float2bfloat16(vx - __bfloat162float(hx));
                    const __nv_bfloat16 ly = __float2bfloat16(vy - __bfloat162float(hy));
                    if (z == 2) {
                        // V^T [b,h,d,t]
                        const size_t a0 = ((size_t)(b * HH + h) * DD + d) * TT + t;
                        g_vth[a0]      = hx;  g_vtl[a0]      = lx;
                        g_vth[a0 + TT] = hy;  g_vtl[a0 + TT] = ly;
                    } else {
                        __nv_bfloat16* dh = (z == 0) ? g_qh : g_kh;
                        __nv_bfloat16* dl = (z == 0) ? g_ql : g_kl;
                        const size_t a0 = ((size_t)(b * HH + h) * TT + t) * DD + d;
                        ushort2 Hu, Lu;
                        Hu.x = __bfloat16_as_ushort(hx); Hu.y = __bfloat16_as_ushort(hy);
                        Lu.x = __bfloat16_as_ushort(lx); Lu.y = __bfloat16_as_ushort(ly);
                        *(ushort2*)&dh[a0] = Hu;
                        *(ushort2*)&dl[a0] = Lu;
                    }
                }
            }
        }
    }
}

// ---------------------------------------------------------------------------
// fp32 -> (hi, lo) bf16 split, vectorized by float4
// ---------------------------------------------------------------------------
__global__ __launch_bounds__(256)
void split_f32(const float4* __restrict__ in, __nv_bfloat16* __restrict__ hi,
               __nv_bfloat16* __restrict__ lo)
{
    const int i = blockIdx.x * 256 + threadIdx.x;
    const float4 v = in[i];
    __nv_bfloat16 h0 = __float2bfloat16(v.x);
    __nv_bfloat16 h1 = __float2bfloat16(v.y);
    __nv_bfloat16 h2 = __float2bfloat16(v.z);
    __nv_bfloat16 h3 = __float2bfloat16(v.w);
    ushort4 H, L;
    H.x = __bfloat16_as_ushort(h0); H.y = __bfloat16_as_ushort(h1);
    H.z = __bfloat16_as_ushort(h2); H.w = __bfloat16_as_ushort(h3);
    L.x = __bfloat16_as_ushort(__float2bfloat16(v.x - __bfloat162float(h0)));
    L.y = __bfloat16_as_ushort(__float2bfloat16(v.y - __bfloat162float(h1)));
    L.z = __bfloat16_as_ushort(__float2bfloat16(v.z - __bfloat162float(h2)));
    L.w = __bfloat16_as_ushort(__float2bfloat16(v.w - __bfloat162float(h3)));
    *(ushort4*)(hi + (size_t)i * 4) = H;
    *(ushort4*)(lo + (size_t)i * 4) = L;
}

// ---------------------------------------------------------------------------
// Transpose + split all 4 weight matrices: W[k][n] fp32 -> Wt hi/lo [n][k] bf16
// ---------------------------------------------------------------------------
__global__ __launch_bounds__(256)
void transpose_split_w(const float* __restrict__ Wq, const float* __restrict__ Wk,
                       const float* __restrict__ Wv, const float* __restrict__ Wo)
{
    __shared__ float tile[32][33];
    const int zz = blockIdx.z;
    const float* W = (zz == 0) ? Wq : (zz == 1) ? Wk : (zz == 2) ? Wv : Wo;
    const int tx = threadIdx.x, ty = threadIdx.y;
    const int n0 = blockIdx.x * 32;
    const int k0 = blockIdx.y * 32;
    #pragma unroll
    for (int i = ty; i < 32; i += 8)
        tile[i][tx] = W[(size_t)(k0 + i) * CC + n0 + tx];
    __syncthreads();
    __nv_bfloat16* oh = g_wth + (size_t)zz * (CC * CC);
    __nv_bfloat16* ol = g_wtl + (size_t)zz * (CC * CC);
    #pragma unroll
    for (int i = ty; i < 32; i += 8) {
        const float v = tile[tx][i];
        const __nv_bfloat16 h = __float2bfloat16(v);
        oh[(size_t)(n0 + i) * CC + k0 + tx] = h;
        ol[(size_t)(n0 + i) * CC + k0 + tx] = __float2bfloat16(v - __bfloat162float(h));
    }
}

// ---------------------------------------------------------------------------
// HMMA flash-attention, causal. 128 q rows/block, 8 warps x 16 rows.
// kv tiles of 64, cp.async double-buffered K(hi/lo) + V^T(hi/lo) tiles.
// S = QhKh + QhKl + QlKh; fp32 online softmax in C fragments; P split hi/lo
// re-packed in-register as A fragments; O = PhVh + PhVl + PlVh.
// Output written as bf16 hi/lo into g_ah/g_al [b,t,c].
// ---------------------------------------------------------------------------
#define SKB 144                       // smem row stride bytes (64 halves + pad)
#define KTB (64*SKB)                  // one 64x64 bf16 tile: 9216 B
#define ATT_STAGE (4*KTB)             // Kh,Kl,Vth,Vtl: 36864 B
#define ATT_SMEM (2*ATT_STAGE)        // 73728 B

__global__ __launch_bounds__(256, 1)
void attn_mma()
{
    extern __shared__ __align__(128) char dsm[];
    const int tid  = threadIdx.x;
    const int wid  = tid >> 5;
    const int lane = tid & 31;
    const int g    = lane >> 2;
    const int tig  = lane & 3;
    const int qb   = (int)gridDim.x - 1 - (int)blockIdx.x;   // long blocks first
    const int bh   = blockIdx.y;
    const int bI   = bh >> 4;
    const int hd   = bh & 15;
    const uint32_t sbase = smem_u32(dsm);
    const float SC = 0.125f * 1.44269504088896340736f;

    // ---- stage Q (hi/lo) into buffer 0, ldmatrix into registers ----
    {
        const size_t qoff = ((size_t)bh * TT + (size_t)qb * 128) * DD;
        #pragma unroll
        for (int i = 0; i < 4; i++) {
            const int idx = i * 256 + tid;           // 0..1023
            const int r = idx >> 3, c = idx & 7;
            CP_ASYNC16(sbase + r * SKB + c * 16,        g_qh + qoff + (size_t)r * DD + c * 8);
            CP_ASYNC16(sbase + 2*KTB + r * SKB + c * 16, g_ql + qoff + (size_t)r * DD + c * 8);
        }
        CP_COMMIT(); CP_WAIT(0);
        __syncthreads();
    }
    uint32_t qhf[4][4], qlf[4][4];
    {
        const uint32_t aB  = sbase + (wid * 16 + (lane & 15)) * SKB + (lane >> 4) * 16;
        #pragma unroll
        for (int kk = 0; kk < 4; kk++) {
            ldmx4(qhf[kk], aB + kk * 32);
            ldmx4(qlf[kk], aB + 2*KTB + kk * 32);
        }
    }
    __syncthreads();

    float c_o[8][4];
    #pragma unroll
    for (int nt = 0; nt < 8; nt++)
        #pragma unroll
        for (int e = 0; e < 4; e++) c_o[nt][e] = 0.0f;
    float mI[2] = {-1e30f, -1e30f}, lI[2] = {0.0f, 0.0f};

    auto load_kv = [&](int j, int slot) {
        const uint32_t sb = sbase + slot * ATT_STAGE;
        #pragma unroll
        for (int i = 0; i < 2; i++) {
            const int idx = i * 256 + tid;           // 0..511
            const int r = idx >> 3, c = idx & 7;
            const size_t gk = ((size_t)bh * TT + j * 64 + r) * DD + c * 8;
            CP_ASYNC16(sb + r * SKB + c * 16,       g_kh + gk);
            CP_ASYNC16(sb + KTB + r * SKB + c * 16, g_kl + gk);
            const size_t gv = ((size_t)bh * DD + r) * TT + j * 64 + c * 8;
            CP_ASYNC16(sb + 2*KTB + r * SKB + c * 16, g_vth + gv);
            CP_ASYNC16(sb + 3*KTB + r * SKB + c * 16, g_vtl + gv);
        }
    };

    const int ntiles = 2 * qb + 2;
    load_kv(0, 0); CP_COMMIT();

    for (int j = 0; j < ntiles; j++) {
        if (j + 1 < ntiles) load_kv(j + 1, (j + 1) & 1);
        CP_COMMIT();
        CP_WAIT(1);
        __syncthreads();

        const uint32_t sb = sbase + (j & 1) * ATT_STAGE;
        const uint32_t bB = sb + ((lane & 7) + ((lane >> 4) << 3)) * SKB
                               + ((lane >> 3) & 1) * 16;

        // ---- S = Q K^T (3 passes) ----
        float c_s[8][4];
        #pragma unroll
        for (int nt = 0; nt < 8; nt++)
            #pragma unroll
            for (int e = 0; e < 4; e++) c_s[nt][e] = 0.0f;

        #pragma unroll
        for (int pass = 0; pass < 3; pass++) {
            const uint32_t kOff = (pass == 1) ? KTB : 0;
            uint32_t (*af)[4] = (pass < 2) ? qhf : qlf;
            #pragma unroll
            for (int kk = 0; kk < 4; kk++) {
                uint32_t bf[4][4];
                #pragma unroll
                for (int np = 0; np < 4; np++)
                    ldmx4(bf[np], bB + kOff + np * 16 * SKB + kk * 32);
                #pragma unroll
                for (int np = 0; np < 4; np++) {
                    mma16816(c_s[np * 2 + 0], af[kk], &bf[np][0]);
                    mma16816(c_s[np * 2 + 1], af[kk], &bf[np][2]);
                }
            }
        }

        // ---- online softmax (fp32, in C fragments) ----
        const bool need_mask = (j >= 2 * qb);
        const int jbase = j * 64;
        #pragma unroll
        for (int hh = 0; hh < 2; hh++) {
            const int qrow = qb * 128 + wid * 16 + g + hh * 8;
            #pragma unroll
            for (int nt = 0; nt < 8; nt++)
                #pragma unroll
                for (int e = 0; e < 2; e++) {
                    const float s = c_s[nt][hh * 2 + e];
                    const int col = jbase + nt * 8 + tig * 2 + e;
                    c_s[nt][hh * 2 + e] =
                        (need_mask && col > qrow) ? -1e30f : s * SC;
                }
            float mx = -1e30f;
            #pragma unroll
            for (int nt = 0; nt < 8; nt++) {
                mx = fmaxf(mx, c_s[nt][hh * 2 + 0]);
                mx = fmaxf(mx, c_s[nt][hh * 2 + 1]);
            }
            mx = fmaxf(mx, __shfl_xor_sync(0xffffffffu, mx, 1));
            mx = fmaxf(mx, __shfl_xor_sync(0xffffffffu, mx, 2));
            const float mN = fmaxf(mI[hh], mx);
            const float corr = exp2f(mI[hh] - mN);
            mI[hh] = mN;
            float rs = 0.0f;
            #pragma unroll
            for (int nt = 0; nt < 8; nt++)
                #pragma unroll
                for (int e = 0; e < 2; e++) {
                    const float p = exp2f(c_s[nt][hh * 2 + e] - mN);
                    c_s[nt][hh * 2 + e] = p;
                    rs += p;
                }
            rs += __shfl_xor_sync(0xffffffffu, rs, 1);
            rs += __shfl_xor_sync(0xffffffffu, rs, 2);
            lI[hh] = lI[hh] * corr + rs;
            #pragma unroll
            for (int nt = 0; nt < 8; nt++) {
                c_o[nt][hh * 2 + 0] *= corr;
                c_o[nt][hh * 2 + 1] *= corr;
            }
        }

        // ---- re-pack P as A fragments (hi/lo) ----
        uint32_t phf[4][4], plf[4][4];
        #pragma unroll
        for (int kk = 0; kk < 4; kk++) {
            split2(c_s[2*kk][0],   c_s[2*kk][1],   phf[kk][0], plf[kk][0]);
            split2(c_s[2*kk][2],   c_s[2*kk][3],   phf[kk][1], plf[kk][1]);
            split2(c_s[2*kk+1][0], c_s[2*kk+1][1], phf[kk][2], plf[kk][2]);
            split2(c_s[2*kk+1][2], c_s[2*kk+1][3], phf[kk][3], plf[kk][3]);
        }

        // ---- O += P V (3 passes) ----
        const uint32_t vB = bB + 2 * KTB;
        #pragma unroll
        for (int pass = 0; pass < 3; pass++) {
            const uint32_t vOff = (pass == 1) ? KTB : 0;
            uint32_t (*pf)[4] = (pass < 2) ? phf : plf;
            #pragma unroll
            for (int kk = 0; kk < 4; kk++) {
                uint32_t bf[4][4];
                #pragma unroll
                for (int np = 0; np < 4; np++)
                    ldmx4(bf[np], vB + vOff + np * 16 * SKB + kk * 32);
                #pragma unroll
                for (int np = 0; np < 4; np++) {
                    mma16816(c_o[np * 2 + 0], pf[kk], &bf[np][0]);
                    mma16816(c_o[np * 2 + 1], pf[kk], &bf[np][2]);
                }
            }
        }
        __syncthreads();
    }

    // ---- epilogue: O/l -> bf16 hi/lo into g_ah/g_al [b,t,c] ----
    #pragma unroll
    for (int hh = 0; hh < 2; hh++) {
        const float inv = 1.0f / lI[hh];
        const int t = qb * 128 + wid * 16 + g + hh * 8;
        const size_t rowb = ((size_t)bI * TT + t) * CC + hd * 64;
        #pragma unroll
        for (int nt = 0; nt < 8; nt++) {
            const float v0 = c_o[nt][hh * 2 + 0] * inv;
            const float v1 = c_o[nt][hh * 2 + 1] * inv;
            const __nv_bfloat16 h0 = __float2bfloat16(v0);
            const __nv_bfloat16 h1 = __float2bfloat16(v1);
            ushort2 Hu, Lu;
            Hu.x = __bfloat16_as_ushort(h0);
            Hu.y = __bfloat16_as_ushort(h1);
            Lu.x = __bfloat16_as_ushort(__float2bfloat16(v0 - __bfloat162float(h0)));
            Lu.y = __bfloat16_as_ushort(__float2bfloat16(v1 - __bfloat162float(h1)));
            const size_t a0 = rowb + nt * 8 + tig * 2;
            *(ushort2*)&g_ah[a0] = Hu;
            *(ushort2*)&g_al[a0] = Lu;
        }
    }
}

// ---------------------------------------------------------------------------
extern "C" void kernel_launch(void* const* d_in, const int* in_sizes, int n_in,
                              void* d_out, int out_size)
{
    const float* x  = (const float*)d_in[0];
    const float* Wq = (const float*)d_in[1];
    const float* bq = (const float*)d_in[2];
    const float* Wk = (const float*)d_in[3];
    const float* bk = (const float*)d_in[4];
    const float* Wv = (const float*)d_in[5];
    const float* bv = (const float*)d_in[6];
    const float* Wo = (const float*)d_in[7];
    const float* bo = (const float*)d_in[8];
    float* out = (float*)d_out;

    cudaFuncSetAttribute(gemm_tc<0>, cudaFuncAttributeMaxDynamicSharedMemorySize, GEMM_SMEM);
    cudaFuncSetAttribute(gemm_tc<1>, cudaFuncAttributeMaxDynamicSharedMemorySize, GEMM_SMEM);
    cudaFuncSetAttribute(attn_mma,   cudaFuncAttributeMaxDynamicSharedMemorySize, ATT_SMEM);

    __nv_bfloat16 *xh, *xl, *ah, *al;
    cudaGetSymbolAddress((void**)&xh, g_xh);
    cudaGetSymbolAddress((void**)&xl, g_xl);
    cudaGetSymbolAddress((void**)&ah, g_ah);
    cudaGetSymbolAddress((void**)&al, g_al);

    // split x into bf16 hi/lo, transpose+split all weights
    split_f32<<<MMr * CC / 1024, 256>>>((const float4*)x, xh, xl);
    transpose_split_w<<<dim3(32, 32, 4), dim3(32, 8)>>>(Wq, Wk, Wv, Wo);

    // QKV projections (HMMA) -> bf16 hi/lo Q/K/V^T
    gemm_tc<0><<<dim3(8, 32, 3), 256, GEMM_SMEM>>>(xh, xl, nullptr, bq, bk, bv);

    // attention (HMMA) -> bf16 hi/lo attn output
    attn_mma<<<dim3(16, 32), 256, ATT_SMEM>>>();

    // output projection (HMMA)
    gemm_tc<1><<<dim3(8, 32, 1), 256, GEMM_SMEM>>>(ah, al, out, bo, bo, bo);
}